// round 15
// baseline (speedup 1.0000x reference)
#include <cuda_runtime.h>
#include <cuda_bf16.h>
#include <cstdint>

// Problem constants (fixed shapes)
#define D_MODEL 1024
#define RANK    256
#define R2      (2*RANK)          // 512
#define NPROJ   (R2 + R2 + RANK)  // 1280 = [a_b|a_t | c_b|c_t | z]
#define BATCH   4
#define SEQ     2048
#define MTOT    (BATCH*SEQ)       // 8192
#define TCH     128
#define NCH     (SEQ/TCH)         // 16
#define SCANC   (R2 + RANK)       // 768 scanned columns
#define PSLICE  (1024*1024 + 1024*512)   // 1.5M floats per k-slice partial

// ---------------- scratch (device globals; no cudaMalloc allowed) ------------
__device__ float         g_H   [MTOT*NPROJ];   // reused as prep partial scratch first
__device__ __nv_bfloat16 g_xh  [MTOT*D_MODEL];
__device__ __nv_bfloat16 g_xl  [MTOT*D_MODEL];
__device__ __nv_bfloat16 g_Gh  [MTOT*R2];
__device__ __nv_bfloat16 g_Gl  [MTOT*R2];
__device__ __nv_bfloat16 g_Bph [NPROJ*D_MODEL];
__device__ __nv_bfloat16 g_Bpl [NPROJ*D_MODEL];
__device__ __nv_bfloat16 g_UWoh[D_MODEL*R2];
__device__ __nv_bfloat16 g_UWol[D_MODEL*R2];
__device__ __nv_bfloat16 g_WqTh[D_MODEL*D_MODEL], g_WqTl[D_MODEL*D_MODEL];
__device__ __nv_bfloat16 g_WkTh[D_MODEL*D_MODEL], g_WkTl[D_MODEL*D_MODEL];
__device__ __nv_bfloat16 g_VcTh[R2*D_MODEL],      g_VcTl[R2*D_MODEL];
__device__ __nv_bfloat16 g_WcTh[R2*D_MODEL],      g_WcTl[R2*D_MODEL];
__device__ __nv_bfloat16 g_UcTh[R2*D_MODEL],      g_UcTl[R2*D_MODEL];
__device__ __nv_bfloat16 g_Woh [D_MODEL*D_MODEL], g_Wol [D_MODEL*D_MODEL];
__device__ float g_bo [D_MODEL];
__device__ float g_cs [BATCH*NCH*SCANC];

// ====================== helpers ==============================================
#define LDSM_X4(R, A) \
    asm volatile("ldmatrix.sync.aligned.m8n8.x4.shared.b16 {%0,%1,%2,%3}, [%4];" \
        : "=r"((R)[0]), "=r"((R)[1]), "=r"((R)[2]), "=r"((R)[3]) : "r"(A))
#define MMA_BF16(D, Ar, Br) \
    asm volatile("mma.sync.aligned.m16n8k16.row.col.f32.bf16.bf16.f32 " \
        "{%0,%1,%2,%3}, {%4,%5,%6,%7}, {%8,%9}, {%0,%1,%2,%3};" \
        : "+f"((D)[0]), "+f"((D)[1]), "+f"((D)[2]), "+f"((D)[3]) \
        : "r"((Ar)[0]), "r"((Ar)[1]), "r"((Ar)[2]), "r"((Ar)[3]), \
          "r"((Br)[0]), "r"((Br)[1]))

__device__ __forceinline__ uint32_t smem_u32(const void* p) {
    uint32_t a;
    asm("{ .reg .u64 t; cvta.to.shared.u64 t, %1; cvt.u32.u64 %0, t; }" : "=r"(a) : "l"(p));
    return a;
}

// paired-row swizzled byte offset (64B logical rows in 128B physical rows)
__device__ __forceinline__ uint32_t swoff(int m, int c) {
    const int p  = m >> 1;
    const int cc = (((m & 1) << 2) | c) ^ (p & 7);
    return (uint32_t)(p * 128 + cc * 16);
}

__device__ __forceinline__ uint32_t pack2(__nv_bfloat16 x, __nv_bfloat16 y) {
    return (uint32_t)__bfloat16_as_ushort(x) | ((uint32_t)__bfloat16_as_ushort(y) << 16);
}

__device__ __forceinline__ void bf_split(float v, __nv_bfloat16& h, __nv_bfloat16& l) {
    h = __float2bfloat16(v);
    l = __float2bfloat16(v - __bfloat162float(h));
}

__device__ __forceinline__ void cpasync16(uint32_t dst, const void* src) {
    asm volatile("cp.async.cg.shared.global [%0], [%1], 16;" :: "r"(dst), "l"(src));
}
#define CP_COMMIT() asm volatile("cp.async.commit_group;" ::: "memory")
#define CP_WAIT1()  asm volatile("cp.async.wait_group 1;"  ::: "memory")

// ====================== shared 4-warp GEMM core ===============================
// 128x128 CTA tile, 4 warps, warp tile 128x32 (1x4 arrangement), BK=32,
// 3-stage cp.async, 96 KB smem, 2 CTAs/SM.
// Per warp per kg: 16 A-LDSM + 4 B-LDSM feed 96 MMAs.
#define TILE_B     8192
#define STAGE_B    32768
#define PRE_SMEM   (3*STAGE_B)   // 96 KB

__device__ __forceinline__ void gemm_core4(
    const __nv_bfloat16* __restrict__ Ah_g, const __nv_bfloat16* __restrict__ Al_g,
    const __nv_bfloat16* __restrict__ Bh_g, const __nv_bfloat16* __restrict__ Bl_g,
    int K, int kbeg, int kend, long bm, long bn, uint32_t sb, float acc[8][4][4])
{
    const int tid = threadIdx.x, wid = tid >> 5, lane = tid & 31;
    const int warpN = wid;                     // 1 x 4, warp tile 128x32

    uint32_t offA0[2], offB0[2];
#pragma unroll
    for (int kg = 0; kg < 2; kg++) {
        offA0[kg] = swoff(lane & 15, 2 * kg + (lane >> 4));
        offB0[kg] = swoff(warpN * 32 + ((lane >> 4) << 3) + (lane & 7),
                          2 * kg + ((lane >> 3) & 1));
    }

    // cp.async: 2048 chunks/stage, 128 threads -> 16 per thread
    const int mrow = tid >> 2, mc = tid & 3;   // rows 0..31, chunks 0..3
    uint32_t soA[4];
#pragma unroll
    for (int rep = 0; rep < 4; rep++) soA[rep] = swoff(mrow + 32 * rep, mc);

    auto issue = [&](int kt) {
        const uint32_t base = sb + (uint32_t)(kt % 3) * STAGE_B;
        const long koff = (long)kt * 32 + mc * 8;
#pragma unroll
        for (int rep = 0; rep < 4; rep++) {
            const long gA = (bm + mrow + 32 * rep) * (long)K + koff;
            const long gB = (bn + mrow + 32 * rep) * (long)K + koff;
            cpasync16(base + soA[rep],            Ah_g + gA);
            cpasync16(base + TILE_B + soA[rep],   Al_g + gA);
            cpasync16(base + 2*TILE_B + soA[rep], Bh_g + gB);
            cpasync16(base + 3*TILE_B + soA[rep], Bl_g + gB);
        }
    };

    issue(kbeg);     CP_COMMIT();
    issue(kbeg + 1); CP_COMMIT();

#pragma unroll 1
    for (int kt = kbeg; kt < kend; kt++) {
        CP_WAIT1();
        __syncthreads();
        if (kt + 2 < kend) issue(kt + 2);
        CP_COMMIT();

        const uint32_t bb = sb + (uint32_t)(kt % 3) * STAGE_B;
#pragma unroll
        for (int kg = 0; kg < 2; kg++) {
            uint32_t bh[4][2], bl[4][2];
#pragma unroll
            for (int jp = 0; jp < 2; jp++) {
                uint32_t rh[4], rl[4];
                const uint32_t bo_ = offB0[kg] + (uint32_t)jp * 1024;
                LDSM_X4(rh, bb + 2*TILE_B + bo_);
                LDSM_X4(rl, bb + 3*TILE_B + bo_);
                bh[2*jp][0]   = rh[0]; bh[2*jp][1]   = rh[1];
                bh[2*jp+1][0] = rh[2]; bh[2*jp+1][1] = rh[3];
                bl[2*jp][0]   = rl[0]; bl[2*jp][1]   = rl[1];
                bl[2*jp+1][0] = rl[2]; bl[2*jp+1][1] = rl[3];
            }
#pragma unroll
            for (int i = 0; i < 8; i++) {
                uint32_t ah[4], al[4];
                const uint32_t ao = bb + offA0[kg] + (uint32_t)i * 1024;
                LDSM_X4(ah, ao);
                LDSM_X4(al, ao + TILE_B);
#pragma unroll
                for (int j = 0; j < 4; j++) {
                    MMA_BF16(acc[i][j], ah, bh[j]);
                    MMA_BF16(acc[i][j], ah, bl[j]);
                    MMA_BF16(acc[i][j], al, bh[j]);
                }
            }
        }
    }
}

// ---------------- main GEMM (fp32 output, optional bias) ---------------------
template<bool BIAS>
__global__ __launch_bounds__(128, 2)
void gemm_main(const __nv_bfloat16* __restrict__ Ah_g, const __nv_bfloat16* __restrict__ Al_g,
               const __nv_bfloat16* __restrict__ Bh_g, const __nv_bfloat16* __restrict__ Bl_g,
               float* __restrict__ C, int N, int K, const float* __restrict__ bias)
{
    extern __shared__ __align__(128) char sm[];
    const uint32_t sb = smem_u32(sm);
    const long bm = (long)blockIdx.y * 128, bn = (long)blockIdx.x * 128;

    float acc[8][4][4];
#pragma unroll
    for (int i = 0; i < 8; i++)
#pragma unroll
        for (int j = 0; j < 4; j++)
#pragma unroll
            for (int q = 0; q < 4; q++) acc[i][j][q] = 0.f;

    gemm_core4(Ah_g, Al_g, Bh_g, Bl_g, K, 0, K / 32, bm, bn, sb, acc);

    const int tid = threadIdx.x, wid = tid >> 5, lane = tid & 31;
    const int warpN = wid;
    const int g = lane >> 2, tg = lane & 3;
#pragma unroll
    for (int i = 0; i < 8; i++) {
        const long row = bm + i * 16 + g;
#pragma unroll
        for (int j = 0; j < 4; j++) {
            const int col = (int)bn + warpN * 32 + j * 8 + 2 * tg;
            float b0 = 0.f, b1 = 0.f;
            if (BIAS) { b0 = bias[col]; b1 = bias[col + 1]; }
            float2 v0 = make_float2(acc[i][j][0] + b0, acc[i][j][1] + b1);
            float2 v1 = make_float2(acc[i][j][2] + b0, acc[i][j][3] + b1);
            *(float2*)(C + row * N + col)       = v0;
            *(float2*)(C + (row + 8) * N + col) = v1;
        }
    }
}

// ---------------- prep GEMM: compact tiles, split-K x3, 4-warp core ----------
__global__ __launch_bounds__(128, 2)
void gemm_prep(const __nv_bfloat16* __restrict__ VcTh, const __nv_bfloat16* __restrict__ VcTl,
               const __nv_bfloat16* __restrict__ WqTh, const __nv_bfloat16* __restrict__ WqTl,
               const __nv_bfloat16* __restrict__ WcTh, const __nv_bfloat16* __restrict__ WcTl,
               const __nv_bfloat16* __restrict__ WkTh, const __nv_bfloat16* __restrict__ WkTl,
               const __nv_bfloat16* __restrict__ Woh,  const __nv_bfloat16* __restrict__ Wol,
               const __nv_bfloat16* __restrict__ UcTh, const __nv_bfloat16* __restrict__ UcTl,
               float* __restrict__ P)
{
    const int t = blockIdx.x, s = blockIdx.y;
    const __nv_bfloat16 *Ah, *Al, *Bh, *Bl;
    long bm, bn, ooff; int ldc;
    if (t < 32)      { Ah=VcTh; Al=VcTl; Bh=WqTh; Bl=WqTl; bm=(t>>3)*128;      bn=(t&7)*128;      ldc=1024; ooff=0; }
    else if (t < 64) { Ah=WcTh; Al=WcTl; Bh=WkTh; Bl=WkTl; bm=((t-32)>>3)*128; bn=((t-32)&7)*128; ldc=1024; ooff=512L*1024; }
    else             { Ah=Woh;  Al=Wol;  Bh=UcTh; Bl=UcTl; bm=((t-64)>>2)*128; bn=((t-64)&3)*128; ldc=512;  ooff=1024L*1024; }
    const int K = 1024;
    const int kbeg = s * 11, kend = (s == 2) ? 32 : kbeg + 11;
    float* Cp = P + (long)s * PSLICE + ooff;

    extern __shared__ __align__(128) char sm[];
    const uint32_t sb = smem_u32(sm);

    float acc[8][4][4];
#pragma unroll
    for (int i = 0; i < 8; i++)
#pragma unroll
        for (int j = 0; j < 4; j++)
#pragma unroll
            for (int q = 0; q < 4; q++) acc[i][j][q] = 0.f;

    gemm_core4(Ah, Al, Bh, Bl, K, kbeg, kend, bm, bn, sb, acc);

    const int tid = threadIdx.x, wid = tid >> 5, lane = tid & 31;
    const int warpN = wid;
    const int g = lane >> 2, tg = lane & 3;
#pragma unroll
    for (int i = 0; i < 8; i++) {
        const long row = bm + i * 16 + g;
#pragma unroll
        for (int j = 0; j < 4; j++) {
            const int col = (int)bn + warpN * 32 + j * 8 + 2 * tg;
            *(float2*)(Cp + row * ldc + col)       = make_float2(acc[i][j][0], acc[i][j][1]);
            *(float2*)(Cp + (row + 8) * ldc + col) = make_float2(acc[i][j][2], acc[i][j][3]);
        }
    }
}

// combine 3 k-slice partials -> bf16 hi/lo planes
__global__ void combine_prep(const float* __restrict__ P,
                             __nv_bfloat16* __restrict__ Bph, __nv_bfloat16* __restrict__ Bpl,
                             __nv_bfloat16* __restrict__ UWoh, __nv_bfloat16* __restrict__ UWol)
{
    const long n = PSLICE;
    for (long i = (long)blockIdx.x * blockDim.x + threadIdx.x; i < n;
         i += (long)gridDim.x * blockDim.x) {
        const float v = P[i] + P[PSLICE + i] + P[2L*PSLICE + i];
        __nv_bfloat16 h, l;
        bf_split(v, h, l);
        if (i < 1024L * 1024) { Bph[i] = h; Bpl[i] = l; }
        else { UWoh[i - 1024L*1024] = h; UWol[i - 1024L*1024] = l; }
    }
}

// ====================== batched transpose / concat / split ===================
__global__ void trans_batched(const float* __restrict__ Wq, const float* __restrict__ Wk,
                              const float* __restrict__ V_b, const float* __restrict__ V_t,
                              const float* __restrict__ W_b, const float* __restrict__ W_t,
                              const float* __restrict__ U_b, const float* __restrict__ U_t,
                              const float* __restrict__ X_t, const float* __restrict__ Wo,
                              __nv_bfloat16* __restrict__ WqTh, __nv_bfloat16* __restrict__ WqTl,
                              __nv_bfloat16* __restrict__ WkTh, __nv_bfloat16* __restrict__ WkTl,
                              __nv_bfloat16* __restrict__ VcTh, __nv_bfloat16* __restrict__ VcTl,
                              __nv_bfloat16* __restrict__ WcTh, __nv_bfloat16* __restrict__ WcTl,
                              __nv_bfloat16* __restrict__ UcTh, __nv_bfloat16* __restrict__ UcTl,
                              __nv_bfloat16* __restrict__ Bph,  __nv_bfloat16* __restrict__ Bpl,
                              __nv_bfloat16* __restrict__ Woh,  __nv_bfloat16* __restrict__ Wol)
{
    __shared__ float t[32][33];
    const int z = blockIdx.z;
    const int bx = blockIdx.x, by = blockIdx.y;
    const int tx = threadIdx.x, ty = threadIdx.y;

    if (z == 9) {
#pragma unroll
        for (int j = 0; j < 32; j += 8) {
            const long o = (long)(by * 32 + ty + j) * 1024 + bx * 32 + tx;
            __nv_bfloat16 h, l;
            bf_split(Wo[o], h, l);
            Woh[o] = h; Wol[o] = l;
        }
        return;
    }

    const float* src; int Cin;
    __nv_bfloat16 *Dh, *Dl; int roff = 0;
    switch (z) {
        case 0: src = Wq;  Cin = 1024; Dh = WqTh; Dl = WqTl; break;
        case 1: src = Wk;  Cin = 1024; Dh = WkTh; Dl = WkTl; break;
        case 2: src = V_b; Cin = 256;  Dh = VcTh; Dl = VcTl; roff = 0;    break;
        case 3: src = V_t; Cin = 256;  Dh = VcTh; Dl = VcTl; roff = 256;  break;
        case 4: src = W_b; Cin = 256;  Dh = WcTh; Dl = WcTl; roff = 0;    break;
        case 5: src = W_t; Cin = 256;  Dh = WcTh; Dl = WcTl; roff = 256;  break;
        case 6: src = U_b; Cin = 256;  Dh = UcTh; Dl = UcTl; roff = 0;    break;
        case 7: src = U_t; Cin = 256;  Dh = UcTh; Dl = UcTl; roff = 256;  break;
        default: src = X_t; Cin = 256; Dh = Bph;  Dl = Bpl;  roff = 1024; break;
    }
    if (Cin == 256 && bx >= 8) return;
#pragma unroll
    for (int j = 0; j < 32; j += 8)
        t[ty + j][tx] = src[(long)(by * 32 + ty + j) * Cin + bx * 32 + tx];
    __syncthreads();
#pragma unroll
    for (int j = 0; j < 32; j += 8) {
        __nv_bfloat16 h, l;
        bf_split(t[tx][ty + j], h, l);
        const long o = (long)(roff + bx * 32 + ty + j) * 1024 + by * 32 + tx;
        Dh[o] = h; Dl[o] = l;
    }
}

// ---------------- split x into bf16 hi/lo planes -----------------------------
__global__ void split_x(const float* __restrict__ x,
                        __nv_bfloat16* __restrict__ xh, __nv_bfloat16* __restrict__ xl)
{
    const long n4 = (long)MTOT * D_MODEL / 4;
    for (long i = (long)blockIdx.x * blockDim.x + threadIdx.x; i < n4;
         i += (long)gridDim.x * blockDim.x) {
        float4 v = ((const float4*)x)[i];
        __nv_bfloat16 h[4], l[4];
        bf_split(v.x, h[0], l[0]); bf_split(v.y, h[1], l[1]);
        bf_split(v.z, h[2], l[2]); bf_split(v.w, h[3], l[3]);
        uint2 H, L;
        H.x = pack2(h[0], h[1]); H.y = pack2(h[2], h[3]);
        L.x = pack2(l[0], l[1]); L.y = pack2(l[2], l[3]);
        ((uint2*)xh)[i] = H;
        ((uint2*)xl)[i] = L;
    }
}

// ---------------- causal cumulative scan (cols 512..1280 of H), float2 -------
__global__ void scan_partial(float* __restrict__ Hc, float* __restrict__ cs)
{
    const int col2 = (blockIdx.x * 128 + threadIdx.x) * 2;   // 0..766 step 2
    const int ch  = blockIdx.y;
    const int b   = blockIdx.z;
    const long base = ((long)b * SEQ + (long)ch * TCH) * NPROJ + col2;
    float2 run = make_float2(0.f, 0.f);
    for (int t = 0; t < TCH; t++) {
        float2 v = *(float2*)(Hc + base + (long)t * NPROJ);
        run.x += v.x; run.y += v.y;
        *(float2*)(Hc + base + (long)t * NPROJ) = run;
    }
    *(float2*)(cs + ((long)b * NCH + ch) * SCANC + col2) = run;
}

__global__ void scan_offsets(float* __restrict__ cs)
{
    const int i = blockIdx.x * blockDim.x + threadIdx.x;
    if (i >= BATCH * SCANC) return;
    const int b = i / SCANC, col = i % SCANC;
    float off = 0.f;
    for (int ch = 0; ch < NCH; ch++) {
        const long idx = ((long)b * NCH + ch) * SCANC + col;
        const float v = cs[idx];
        cs[idx] = off;
        off += v;
    }
}

// ---------------- fused scan-apply + G build (bf16 split, float2) ------------
__global__ void apply_build(const float* __restrict__ H, const float* __restrict__ cs,
                            const float* __restrict__ alpha,
                            __nv_bfloat16* __restrict__ Gh, __nv_bfloat16* __restrict__ Gl)
{
    const int i = blockIdx.x * blockDim.x + threadIdx.x;  // MTOT * 128 threads
    if (i >= MTOT * (RANK / 2)) return;
    const int m = i / (RANK / 2), rr = (i % (RANK / 2)) * 2;
    const int t = m % SEQ, b = m / SEQ, ch = t / TCH;
    const float inv = 1.0f / (float)(t + 1);
    const float* hrow = H + (long)m * NPROJ;
    const float* co = cs + ((long)b * NCH + ch) * SCANC;

    const float2 ab = *(const float2*)(hrow + rr);
    const float2 at = *(const float2*)(hrow + 256 + rr);
    const float2 pb = *(const float2*)(hrow + 512 + rr);
    const float2 pt = *(const float2*)(hrow + 768 + rr);
    const float2 pz = *(const float2*)(hrow + 1024 + rr);
    const float2 ob = *(const float2*)(co + rr);
    const float2 ot = *(const float2*)(co + 256 + rr);
    const float2 oz = *(const float2*)(co + 512 + rr);
    const float a = alpha[0];

    const float gb0 = ab.x * (pb.x + ob.x) * inv;
    const float gb1 = ab.y * (pb.y + ob.y) * inv;
    const float gt0 = a * at.x * ((pz.x + oz.x) * inv) * (pt.x + ot.x) * inv;
    const float gt1 = a * at.y * ((pz.y + oz.y) * inv) * (pt.y + ot.y) * inv;

    const long o = (long)m * R2 + rr;
    __nv_bfloat16 h0, l0, h1, l1;
    bf_split(gb0, h0, l0); bf_split(gb1, h1, l1);
    *(uint32_t*)(Gh + o) = pack2(h0, h1);
    *(uint32_t*)(Gl + o) = pack2(l0, l1);
    bf_split(gt0, h0, l0); bf_split(gt1, h1, l1);
    *(uint32_t*)(Gh + o + RANK) = pack2(h0, h1);
    *(uint32_t*)(Gl + o + RANK) = pack2(l0, l1);
}

// bo[d] = sum_e Wo[d,e] * (bias_b[e] + alpha*bias_t[e])
__global__ void bo_kernel(const float* __restrict__ Wo, const float* __restrict__ bb,
                          const float* __restrict__ bt, const float* __restrict__ alpha,
                          float* __restrict__ bo)
{
    const int w = (blockIdx.x * blockDim.x + threadIdx.x) >> 5;
    const int lane = threadIdx.x & 31;
    if (w >= D_MODEL) return;
    const float a = alpha[0];
    float s = 0.f;
    for (int e = lane; e < D_MODEL; e += 32)
        s += Wo[(long)w * D_MODEL + e] * (bb[e] + a * bt[e]);
#pragma unroll
    for (int o = 16; o; o >>= 1) s += __shfl_xor_sync(0xFFFFFFFFu, s, o);
    if (lane == 0) bo[w] = s;
}

// ---------------- launch ------------------------------------------------------
extern "C" void kernel_launch(void* const* d_in, const int* in_sizes, int n_in,
                              void* d_out, int out_size)
{
    const float* x      = (const float*)d_in[0];
    const float* Wq     = (const float*)d_in[1];
    const float* Wk     = (const float*)d_in[2];
    const float* Wo     = (const float*)d_in[3];
    const float* U_b    = (const float*)d_in[4];
    const float* V_b    = (const float*)d_in[5];
    const float* W_b    = (const float*)d_in[6];
    const float* bias_b = (const float*)d_in[7];
    const float* U_t    = (const float*)d_in[8];
    const float* V_t    = (const float*)d_in[9];
    const float* W_t    = (const float*)d_in[10];
    const float* X_t    = (const float*)d_in[11];
    const float* bias_t = (const float*)d_in[12];
    const float* alpha  = (const float*)d_in[13];
    float* out = (float*)d_out;

    float *H, *bo, *cs;
    __nv_bfloat16 *xh, *xl, *Gh, *Gl, *Bph, *Bpl, *UWoh, *UWol;
    __nv_bfloat16 *WqTh, *WqTl, *WkTh, *WkTl, *VcTh, *VcTl, *WcTh, *WcTl, *UcTh, *UcTl, *Woh, *Wol;
    cudaGetSymbolAddress((void**)&H,    g_H);
    cudaGetSymbolAddress((void**)&xh,   g_xh);
    cudaGetSymbolAddress((void**)&xl,   g_xl);
    cudaGetSymbolAddress((void**)&Gh,   g_Gh);
    cudaGetSymbolAddress((void**)&Gl,   g_Gl);
    cudaGetSymbolAddress((void**)&Bph,  g_Bph);
    cudaGetSymbolAddress((void**)&Bpl,  g_Bpl);
    cudaGetSymbolAddress((void**)&UWoh, g_UWoh);
    cudaGetSymbolAddress((void**)&UWol, g_UWol);
    cudaGetSymbolAddress((void**)&WqTh, g_WqTh);
    cudaGetSymbolAddress((void**)&WqTl, g_WqTl);
    cudaGetSymbolAddress((void**)&WkTh, g_WkTh);
    cudaGetSymbolAddress((void**)&WkTl, g_WkTl);
    cudaGetSymbolAddress((void**)&VcTh, g_VcTh);
    cudaGetSymbolAddress((void**)&VcTl, g_VcTl);
    cudaGetSymbolAddress((void**)&WcTh, g_WcTh);
    cudaGetSymbolAddress((void**)&WcTl, g_WcTl);
    cudaGetSymbolAddress((void**)&UcTh, g_UcTh);
    cudaGetSymbolAddress((void**)&UcTl, g_UcTl);
    cudaGetSymbolAddress((void**)&Woh,  g_Woh);
    cudaGetSymbolAddress((void**)&Wol,  g_Wol);
    cudaGetSymbolAddress((void**)&bo,   g_bo);
    cudaGetSymbolAddress((void**)&cs,   g_cs);

    cudaFuncSetAttribute(gemm_prep,        cudaFuncAttributeMaxDynamicSharedMemorySize, PRE_SMEM);
    cudaFuncSetAttribute(gemm_main<false>, cudaFuncAttributeMaxDynamicSharedMemorySize, PRE_SMEM);
    cudaFuncSetAttribute(gemm_main<true>,  cudaFuncAttributeMaxDynamicSharedMemorySize, PRE_SMEM);

    // ---- prep: transposes/concats + bias fold + x split ----
    dim3 tgrid(32, 32, 10), tblk(32, 8);
    trans_batched<<<tgrid, tblk>>>(Wq, Wk, V_b, V_t, W_b, W_t, U_b, U_t, X_t, Wo,
                                   WqTh, WqTl, WkTh, WkTl, VcTh, VcTl, WcTh, WcTl,
                                   UcTh, UcTl, Bph, Bpl, Woh, Wol);
    bo_kernel<<<128, 256>>>(Wo, bias_b, bias_t, alpha, bo);
    split_x<<<4096, 256>>>(x, xh, xl);

    // ---- prep GEMMs: 96 tiles x 3 k-slices = 288 CTAs (one dual-CTA wave) ----
    dim3 gprep(96, 3);
    gemm_prep<<<gprep, 128, PRE_SMEM>>>(VcTh, VcTl, WqTh, WqTl, WcTh, WcTl, WkTh, WkTl,
                                        Woh, Wol, UcTh, UcTl, H);
    combine_prep<<<1024, 256>>>(H, Bph, Bpl, UWoh, UWol);

    // ---- main: H = x @ Bp^T  [8192, 1280] ----
    dim3 gH(NPROJ / 128, MTOT / 128);
    gemm_main<false><<<gH, 128, PRE_SMEM>>>(xh, xl, Bph, Bpl, H, NPROJ, D_MODEL, nullptr);

    // ---- causal scan over H cols [512,1280) (float2: 2 cols/thread) ----
    dim3 gs(SCANC / 256, NCH, BATCH);
    scan_partial<<<gs, 128>>>(H + 512, cs);
    scan_offsets<<<(BATCH * SCANC + 255) / 256, 256>>>(cs);

    // ---- fused apply + build G (bf16 split, 2 r per thread) ----
    apply_build<<<(MTOT * (RANK / 2) + 255) / 256, 256>>>(H, cs, alpha, Gh, Gl);

    // ---- out = G @ UWo^T + bo  [8192, 1024] ----
    dim3 gO(D_MODEL / 128, MTOT / 128);
    gemm_main<true><<<gO, 128, PRE_SMEM>>>(Gh, Gl, UWoh, UWol, out, D_MODEL, R2, bo);
}

// round 16
// speedup vs baseline: 1.0334x; 1.0334x over previous
#include <cuda_runtime.h>
#include <cuda_bf16.h>
#include <cstdint>

// Problem constants (fixed shapes)
#define D_MODEL 1024
#define RANK    256
#define R2      (2*RANK)          // 512
#define NPROJ   (R2 + R2 + RANK)  // 1280 = [a_b|a_t | c_b|c_t | z]
#define BATCH   4
#define SEQ     2048
#define MTOT    (BATCH*SEQ)       // 8192
#define TCH     128
#define NCH     (SEQ/TCH)         // 16
#define SCANC   (R2 + RANK)       // 768 scanned columns
#define PSLICE  (1024*1024 + 1024*512)   // 1.5M floats per k-slice partial

// ---------------- scratch (device globals; no cudaMalloc allowed) ------------
__device__ float         g_H   [MTOT*NPROJ];   // reused as prep partial scratch first
__device__ __nv_bfloat16 g_xh  [MTOT*D_MODEL];
__device__ __nv_bfloat16 g_xl  [MTOT*D_MODEL];
__device__ __nv_bfloat16 g_Gh  [MTOT*R2];
__device__ __nv_bfloat16 g_Gl  [MTOT*R2];
__device__ __nv_bfloat16 g_Bph [NPROJ*D_MODEL];
__device__ __nv_bfloat16 g_Bpl [NPROJ*D_MODEL];
__device__ __nv_bfloat16 g_UWoh[D_MODEL*R2];
__device__ __nv_bfloat16 g_UWol[D_MODEL*R2];
__device__ __nv_bfloat16 g_WqTh[D_MODEL*D_MODEL], g_WqTl[D_MODEL*D_MODEL];
__device__ __nv_bfloat16 g_WkTh[D_MODEL*D_MODEL], g_WkTl[D_MODEL*D_MODEL];
__device__ __nv_bfloat16 g_VcTh[R2*D_MODEL],      g_VcTl[R2*D_MODEL];
__device__ __nv_bfloat16 g_WcTh[R2*D_MODEL],      g_WcTl[R2*D_MODEL];
__device__ __nv_bfloat16 g_UcTh[R2*D_MODEL],      g_UcTl[R2*D_MODEL];
__device__ __nv_bfloat16 g_Woh [D_MODEL*D_MODEL], g_Wol [D_MODEL*D_MODEL];
__device__ float g_bo [D_MODEL];
__device__ float g_cs [BATCH*NCH*SCANC];

// ====================== helpers ==============================================
#define LDSM_X4(R, A) \
    asm volatile("ldmatrix.sync.aligned.m8n8.x4.shared.b16 {%0,%1,%2,%3}, [%4];" \
        : "=r"((R)[0]), "=r"((R)[1]), "=r"((R)[2]), "=r"((R)[3]) : "r"(A))
#define MMA_BF16(D, Ar, Br) \
    asm volatile("mma.sync.aligned.m16n8k16.row.col.f32.bf16.bf16.f32 " \
        "{%0,%1,%2,%3}, {%4,%5,%6,%7}, {%8,%9}, {%0,%1,%2,%3};" \
        : "+f"((D)[0]), "+f"((D)[1]), "+f"((D)[2]), "+f"((D)[3]) \
        : "r"((Ar)[0]), "r"((Ar)[1]), "r"((Ar)[2]), "r"((Ar)[3]), \
          "r"((Br)[0]), "r"((Br)[1]))

__device__ __forceinline__ uint32_t smem_u32(const void* p) {
    uint32_t a;
    asm("{ .reg .u64 t; cvta.to.shared.u64 t, %1; cvt.u32.u64 %0, t; }" : "=r"(a) : "l"(p));
    return a;
}

// paired-row swizzled byte offset (64B logical rows in 128B physical rows)
__device__ __forceinline__ uint32_t swoff(int m, int c) {
    const int p  = m >> 1;
    const int cc = (((m & 1) << 2) | c) ^ (p & 7);
    return (uint32_t)(p * 128 + cc * 16);
}

__device__ __forceinline__ uint32_t pack2(__nv_bfloat16 x, __nv_bfloat16 y) {
    return (uint32_t)__bfloat16_as_ushort(x) | ((uint32_t)__bfloat16_as_ushort(y) << 16);
}

__device__ __forceinline__ void bf_split(float v, __nv_bfloat16& h, __nv_bfloat16& l) {
    h = __float2bfloat16(v);
    l = __float2bfloat16(v - __bfloat162float(h));
}

__device__ __forceinline__ void cpasync16(uint32_t dst, const void* src) {
    asm volatile("cp.async.cg.shared.global [%0], [%1], 16;" :: "r"(dst), "l"(src));
}
#define CP_COMMIT() asm volatile("cp.async.commit_group;" ::: "memory")
#define CP_WAIT1()  asm volatile("cp.async.wait_group 1;"  ::: "memory")

// ====================== shared 4-warp GEMM core (R14: 2x2, 64x64) ============
#define TILE_B     8192
#define STAGE_B    32768
#define PRE_SMEM   (3*STAGE_B)   // 96 KB

__device__ __forceinline__ void gemm_core4(
    const __nv_bfloat16* __restrict__ Ah_g, const __nv_bfloat16* __restrict__ Al_g,
    const __nv_bfloat16* __restrict__ Bh_g, const __nv_bfloat16* __restrict__ Bl_g,
    int K, int kbeg, int kend, long bm, long bn, uint32_t sb, float acc[4][8][4])
{
    const int tid = threadIdx.x, wid = tid >> 5, lane = tid & 31;
    const int warpM = wid & 1, warpN = wid >> 1;      // 2 x 2, 64x64 tiles

    uint32_t offA0[2], offB0[2];
#pragma unroll
    for (int kg = 0; kg < 2; kg++) {
        offA0[kg] = swoff(warpM * 64 + (lane & 15), 2 * kg + (lane >> 4));
        offB0[kg] = swoff(warpN * 64 + ((lane >> 4) << 3) + (lane & 7),
                          2 * kg + ((lane >> 3) & 1));
    }

    const int mrow = tid >> 2, mc = tid & 3;   // rows 0..31, chunks 0..3
    uint32_t soA[4];
#pragma unroll
    for (int rep = 0; rep < 4; rep++) soA[rep] = swoff(mrow + 32 * rep, mc);

    auto issue = [&](int kt) {
        const uint32_t base = sb + (uint32_t)(kt % 3) * STAGE_B;
        const long koff = (long)kt * 32 + mc * 8;
#pragma unroll
        for (int rep = 0; rep < 4; rep++) {
            const long gA = (bm + mrow + 32 * rep) * (long)K + koff;
            const long gB = (bn + mrow + 32 * rep) * (long)K + koff;
            cpasync16(base + soA[rep],            Ah_g + gA);
            cpasync16(base + TILE_B + soA[rep],   Al_g + gA);
            cpasync16(base + 2*TILE_B + soA[rep], Bh_g + gB);
            cpasync16(base + 3*TILE_B + soA[rep], Bl_g + gB);
        }
    };

    issue(kbeg);     CP_COMMIT();
    issue(kbeg + 1); CP_COMMIT();

#pragma unroll 1
    for (int kt = kbeg; kt < kend; kt++) {
        CP_WAIT1();
        __syncthreads();
        if (kt + 2 < kend) issue(kt + 2);
        CP_COMMIT();

        const uint32_t bb = sb + (uint32_t)(kt % 3) * STAGE_B;
#pragma unroll
        for (int kg = 0; kg < 2; kg++) {
            uint32_t bh[8][2], bl[8][2];
#pragma unroll
            for (int jp = 0; jp < 4; jp++) {
                uint32_t rh[4], rl[4];
                const uint32_t bo_ = offB0[kg] + (uint32_t)jp * 1024;
                LDSM_X4(rh, bb + 2*TILE_B + bo_);
                LDSM_X4(rl, bb + 3*TILE_B + bo_);
                bh[2*jp][0]   = rh[0]; bh[2*jp][1]   = rh[1];
                bh[2*jp+1][0] = rh[2]; bh[2*jp+1][1] = rh[3];
                bl[2*jp][0]   = rl[0]; bl[2*jp][1]   = rl[1];
                bl[2*jp+1][0] = rl[2]; bl[2*jp+1][1] = rl[3];
            }
#pragma unroll
            for (int i = 0; i < 4; i++) {
                uint32_t ah[4], al[4];
                const uint32_t ao = bb + offA0[kg] + (uint32_t)i * 1024;
                LDSM_X4(ah, ao);
                LDSM_X4(al, ao + TILE_B);
#pragma unroll
                for (int j = 0; j < 8; j++) {
                    MMA_BF16(acc[i][j], ah, bh[j]);
                    MMA_BF16(acc[i][j], ah, bl[j]);
                    MMA_BF16(acc[i][j], al, bh[j]);
                }
            }
        }
    }
}

// ---------------- main GEMM (fp32 out, optional bias, optional fused scan) ---
// SCANOPT && bn>=512: epilogue dumps tile to smem, computes the within-chunk
// column prefix (rows==chunk), writes prefixed H + chunk totals to cs.
template<bool BIAS, bool SCANOPT>
__global__ __launch_bounds__(128, 2)
void gemm_main(const __nv_bfloat16* __restrict__ Ah_g, const __nv_bfloat16* __restrict__ Al_g,
               const __nv_bfloat16* __restrict__ Bh_g, const __nv_bfloat16* __restrict__ Bl_g,
               float* __restrict__ C, int N, int K, const float* __restrict__ bias,
               float* __restrict__ cs)
{
    extern __shared__ __align__(128) char sm[];
    const uint32_t sb = smem_u32(sm);
    const long bm = (long)blockIdx.y * 128, bn = (long)blockIdx.x * 128;

    float acc[4][8][4];
#pragma unroll
    for (int i = 0; i < 4; i++)
#pragma unroll
        for (int j = 0; j < 8; j++)
#pragma unroll
            for (int q = 0; q < 4; q++) acc[i][j][q] = 0.f;

    gemm_core4(Ah_g, Al_g, Bh_g, Bl_g, K, 0, K / 32, bm, bn, sb, acc);

    const int tid = threadIdx.x, wid = tid >> 5, lane = tid & 31;
    const int warpM = wid & 1, warpN = wid >> 1;
    const int g = lane >> 2, tg = lane & 3;

    if (SCANOPT && bn >= 512) {
        // fused within-chunk prefix scan epilogue
        __syncthreads();   // all warps done with pipeline smem
        float (*ts)[132] = (float(*)[132])sm;
#pragma unroll
        for (int i = 0; i < 4; i++) {
            const int r0 = warpM * 64 + i * 16 + g;
#pragma unroll
            for (int j = 0; j < 8; j++) {
                const int c0 = warpN * 64 + j * 8 + 2 * tg;
                ts[r0][c0]     = acc[i][j][0];
                ts[r0][c0 + 1] = acc[i][j][1];
                ts[r0 + 8][c0]     = acc[i][j][2];
                ts[r0 + 8][c0 + 1] = acc[i][j][3];
            }
        }
        __syncthreads();
        const int col = tid;            // 0..127
        float run = 0.f;
        float* hp = C + bm * N + bn + col;
#pragma unroll 4
        for (int t = 0; t < 128; t++) {
            run += ts[t][col];
            *hp = run;
            hp += N;
        }
        cs[(bm >> 7) * (long)SCANC + (bn - 512) + col] = run;
        return;
    }

#pragma unroll
    for (int i = 0; i < 4; i++) {
        const long row = bm + warpM * 64 + i * 16 + g;
#pragma unroll
        for (int j = 0; j < 8; j++) {
            const int col = (int)bn + warpN * 64 + j * 8 + 2 * tg;
            float b0 = 0.f, b1 = 0.f;
            if (BIAS) { b0 = bias[col]; b1 = bias[col + 1]; }
            float2 v0 = make_float2(acc[i][j][0] + b0, acc[i][j][1] + b1);
            float2 v1 = make_float2(acc[i][j][2] + b0, acc[i][j][3] + b1);
            *(float2*)(C + row * N + col)       = v0;
            *(float2*)(C + (row + 8) * N + col) = v1;
        }
    }
}

// ---------------- prep GEMM: compact tiles, split-K x3, 4-warp core ----------
__global__ __launch_bounds__(128, 2)
void gemm_prep(const __nv_bfloat16* __restrict__ VcTh, const __nv_bfloat16* __restrict__ VcTl,
               const __nv_bfloat16* __restrict__ WqTh, const __nv_bfloat16* __restrict__ WqTl,
               const __nv_bfloat16* __restrict__ WcTh, const __nv_bfloat16* __restrict__ WcTl,
               const __nv_bfloat16* __restrict__ WkTh, const __nv_bfloat16* __restrict__ WkTl,
               const __nv_bfloat16* __restrict__ Woh,  const __nv_bfloat16* __restrict__ Wol,
               const __nv_bfloat16* __restrict__ UcTh, const __nv_bfloat16* __restrict__ UcTl,
               float* __restrict__ P)
{
    const int t = blockIdx.x, s = blockIdx.y;
    const __nv_bfloat16 *Ah, *Al, *Bh, *Bl;
    long bm, bn, ooff; int ldc;
    if (t < 32)      { Ah=VcTh; Al=VcTl; Bh=WqTh; Bl=WqTl; bm=(t>>3)*128;      bn=(t&7)*128;      ldc=1024; ooff=0; }
    else if (t < 64) { Ah=WcTh; Al=WcTl; Bh=WkTh; Bl=WkTl; bm=((t-32)>>3)*128; bn=((t-32)&7)*128; ldc=1024; ooff=512L*1024; }
    else             { Ah=Woh;  Al=Wol;  Bh=UcTh; Bl=UcTl; bm=((t-64)>>2)*128; bn=((t-64)&3)*128; ldc=512;  ooff=1024L*1024; }
    const int K = 1024;
    const int kbeg = s * 11, kend = (s == 2) ? 32 : kbeg + 11;
    float* Cp = P + (long)s * PSLICE + ooff;

    extern __shared__ __align__(128) char sm[];
    const uint32_t sb = smem_u32(sm);

    float acc[4][8][4];
#pragma unroll
    for (int i = 0; i < 4; i++)
#pragma unroll
        for (int j = 0; j < 8; j++)
#pragma unroll
            for (int q = 0; q < 4; q++) acc[i][j][q] = 0.f;

    gemm_core4(Ah, Al, Bh, Bl, K, kbeg, kend, bm, bn, sb, acc);

    const int tid = threadIdx.x, wid = tid >> 5, lane = tid & 31;
    const int warpM = wid & 1, warpN = wid >> 1;
    const int g = lane >> 2, tg = lane & 3;
#pragma unroll
    for (int i = 0; i < 4; i++) {
        const long row = bm + warpM * 64 + i * 16 + g;
#pragma unroll
        for (int j = 0; j < 8; j++) {
            const int col = (int)bn + warpN * 64 + j * 8 + 2 * tg;
            *(float2*)(Cp + row * ldc + col)       = make_float2(acc[i][j][0], acc[i][j][1]);
            *(float2*)(Cp + (row + 8) * ldc + col) = make_float2(acc[i][j][2], acc[i][j][3]);
        }
    }
}

// combine 3 k-slice partials -> bf16 hi/lo planes
__global__ void combine_prep(const float* __restrict__ P,
                             __nv_bfloat16* __restrict__ Bph, __nv_bfloat16* __restrict__ Bpl,
                             __nv_bfloat16* __restrict__ UWoh, __nv_bfloat16* __restrict__ UWol)
{
    const long n = PSLICE;
    for (long i = (long)blockIdx.x * blockDim.x + threadIdx.x; i < n;
         i += (long)gridDim.x * blockDim.x) {
        const float v = P[i] + P[PSLICE + i] + P[2L*PSLICE + i];
        __nv_bfloat16 h, l;
        bf_split(v, h, l);
        if (i < 1024L * 1024) { Bph[i] = h; Bpl[i] = l; }
        else { UWoh[i - 1024L*1024] = h; UWol[i - 1024L*1024] = l; }
    }
}

// ====================== batched transpose / concat / split ===================
__global__ void trans_batched(const float* __restrict__ Wq, const float* __restrict__ Wk,
                              const float* __restrict__ V_b, const float* __restrict__ V_t,
                              const float* __restrict__ W_b, const float* __restrict__ W_t,
                              const float* __restrict__ U_b, const float* __restrict__ U_t,
                              const float* __restrict__ X_t, const float* __restrict__ Wo,
                              __nv_bfloat16* __restrict__ WqTh, __nv_bfloat16* __restrict__ WqTl,
                              __nv_bfloat16* __restrict__ WkTh, __nv_bfloat16* __restrict__ WkTl,
                              __nv_bfloat16* __restrict__ VcTh, __nv_bfloat16* __restrict__ VcTl,
                              __nv_bfloat16* __restrict__ WcTh, __nv_bfloat16* __restrict__ WcTl,
                              __nv_bfloat16* __restrict__ UcTh, __nv_bfloat16* __restrict__ UcTl,
                              __nv_bfloat16* __restrict__ Bph,  __nv_bfloat16* __restrict__ Bpl,
                              __nv_bfloat16* __restrict__ Woh,  __nv_bfloat16* __restrict__ Wol)
{
    __shared__ float t[32][33];
    const int z = blockIdx.z;
    const int bx = blockIdx.x, by = blockIdx.y;
    const int tx = threadIdx.x, ty = threadIdx.y;

    if (z == 9) {
#pragma unroll
        for (int j = 0; j < 32; j += 8) {
            const long o = (long)(by * 32 + ty + j) * 1024 + bx * 32 + tx;
            __nv_bfloat16 h, l;
            bf_split(Wo[o], h, l);
            Woh[o] = h; Wol[o] = l;
        }
        return;
    }

    const float* src; int Cin;
    __nv_bfloat16 *Dh, *Dl; int roff = 0;
    switch (z) {
        case 0: src = Wq;  Cin = 1024; Dh = WqTh; Dl = WqTl; break;
        case 1: src = Wk;  Cin = 1024; Dh = WkTh; Dl = WkTl; break;
        case 2: src = V_b; Cin = 256;  Dh = VcTh; Dl = VcTl; roff = 0;    break;
        case 3: src = V_t; Cin = 256;  Dh = VcTh; Dl = VcTl; roff = 256;  break;
        case 4: src = W_b; Cin = 256;  Dh = WcTh; Dl = WcTl; roff = 0;    break;
        case 5: src = W_t; Cin = 256;  Dh = WcTh; Dl = WcTl; roff = 256;  break;
        case 6: src = U_b; Cin = 256;  Dh = UcTh; Dl = UcTl; roff = 0;    break;
        case 7: src = U_t; Cin = 256;  Dh = UcTh; Dl = UcTl; roff = 256;  break;
        default: src = X_t; Cin = 256; Dh = Bph;  Dl = Bpl;  roff = 1024; break;
    }
    if (Cin == 256 && bx >= 8) return;
#pragma unroll
    for (int j = 0; j < 32; j += 8)
        t[ty + j][tx] = src[(long)(by * 32 + ty + j) * Cin + bx * 32 + tx];
    __syncthreads();
#pragma unroll
    for (int j = 0; j < 32; j += 8) {
        __nv_bfloat16 h, l;
        bf_split(t[tx][ty + j], h, l);
        const long o = (long)(roff + bx * 32 + ty + j) * 1024 + by * 32 + tx;
        Dh[o] = h; Dl[o] = l;
    }
}

// ---------------- split x into bf16 hi/lo planes -----------------------------
__global__ void split_x(const float* __restrict__ x,
                        __nv_bfloat16* __restrict__ xh, __nv_bfloat16* __restrict__ xl)
{
    const long n4 = (long)MTOT * D_MODEL / 4;
    for (long i = (long)blockIdx.x * blockDim.x + threadIdx.x; i < n4;
         i += (long)gridDim.x * blockDim.x) {
        float4 v = ((const float4*)x)[i];
        __nv_bfloat16 h[4], l[4];
        bf_split(v.x, h[0], l[0]); bf_split(v.y, h[1], l[1]);
        bf_split(v.z, h[2], l[2]); bf_split(v.w, h[3], l[3]);
        uint2 H, L;
        H.x = pack2(h[0], h[1]); H.y = pack2(h[2], h[3]);
        L.x = pack2(l[0], l[1]); L.y = pack2(l[2], l[3]);
        ((uint2*)xh)[i] = H;
        ((uint2*)xl)[i] = L;
    }
}

__global__ void scan_offsets(float* __restrict__ cs)
{
    const int i = blockIdx.x * blockDim.x + threadIdx.x;
    if (i >= BATCH * SCANC) return;
    const int b = i / SCANC, col = i % SCANC;
    float off = 0.f;
    for (int ch = 0; ch < NCH; ch++) {
        const long idx = ((long)b * NCH + ch) * SCANC + col;
        const float v = cs[idx];
        cs[idx] = off;
        off += v;
    }
}

// ---------------- fused scan-apply + G build (bf16 split, float2) ------------
__global__ void apply_build(const float* __restrict__ H, const float* __restrict__ cs,
                            const float* __restrict__ alpha,
                            __nv_bfloat16* __restrict__ Gh, __nv_bfloat16* __restrict__ Gl)
{
    const int i = blockIdx.x * blockDim.x + threadIdx.x;  // MTOT * 128 threads
    if (i >= MTOT * (RANK / 2)) return;
    const int m = i / (RANK / 2), rr = (i % (RANK / 2)) * 2;
    const int t = m % SEQ, b = m / SEQ, ch = t / TCH;
    const float inv = 1.0f / (float)(t + 1);
    const float* hrow = H + (long)m * NPROJ;
    const float* co = cs + ((long)b * NCH + ch) * SCANC;

    const float2 ab = *(const float2*)(hrow + rr);
    const float2 at = *(const float2*)(hrow + 256 + rr);
    const float2 pb = *(const float2*)(hrow + 512 + rr);
    const float2 pt = *(const float2*)(hrow + 768 + rr);
    const float2 pz = *(const float2*)(hrow + 1024 + rr);
    const float2 ob = *(const float2*)(co + rr);
    const float2 ot = *(const float2*)(co + 256 + rr);
    const float2 oz = *(const float2*)(co + 512 + rr);
    const float a = alpha[0];

    const float gb0 = ab.x * (pb.x + ob.x) * inv;
    const float gb1 = ab.y * (pb.y + ob.y) * inv;
    const float gt0 = a * at.x * ((pz.x + oz.x) * inv) * (pt.x + ot.x) * inv;
    const float gt1 = a * at.y * ((pz.y + oz.y) * inv) * (pt.y + ot.y) * inv;

    const long o = (long)m * R2 + rr;
    __nv_bfloat16 h0, l0, h1, l1;
    bf_split(gb0, h0, l0); bf_split(gb1, h1, l1);
    *(uint32_t*)(Gh + o) = pack2(h0, h1);
    *(uint32_t*)(Gl + o) = pack2(l0, l1);
    bf_split(gt0, h0, l0); bf_split(gt1, h1, l1);
    *(uint32_t*)(Gh + o + RANK) = pack2(h0, h1);
    *(uint32_t*)(Gl + o + RANK) = pack2(l0, l1);
}

// bo[d] = sum_e Wo[d,e] * (bias_b[e] + alpha*bias_t[e])
__global__ void bo_kernel(const float* __restrict__ Wo, const float* __restrict__ bb,
                          const float* __restrict__ bt, const float* __restrict__ alpha,
                          float* __restrict__ bo)
{
    const int w = (blockIdx.x * blockDim.x + threadIdx.x) >> 5;
    const int lane = threadIdx.x & 31;
    if (w >= D_MODEL) return;
    const float a = alpha[0];
    float s = 0.f;
    for (int e = lane; e < D_MODEL; e += 32)
        s += Wo[(long)w * D_MODEL + e] * (bb[e] + a * bt[e]);
#pragma unroll
    for (int o = 16; o; o >>= 1) s += __shfl_xor_sync(0xFFFFFFFFu, s, o);
    if (lane == 0) bo[w] = s;
}

// ---------------- launch ------------------------------------------------------
extern "C" void kernel_launch(void* const* d_in, const int* in_sizes, int n_in,
                              void* d_out, int out_size)
{
    const float* x      = (const float*)d_in[0];
    const float* Wq     = (const float*)d_in[1];
    const float* Wk     = (const float*)d_in[2];
    const float* Wo     = (const float*)d_in[3];
    const float* U_b    = (const float*)d_in[4];
    const float* V_b    = (const float*)d_in[5];
    const float* W_b    = (const float*)d_in[6];
    const float* bias_b = (const float*)d_in[7];
    const float* U_t    = (const float*)d_in[8];
    const float* V_t    = (const float*)d_in[9];
    const float* W_t    = (const float*)d_in[10];
    const float* X_t    = (const float*)d_in[11];
    const float* bias_t = (const float*)d_in[12];
    const float* alpha  = (const float*)d_in[13];
    float* out = (float*)d_out;

    float *H, *bo, *cs;
    __nv_bfloat16 *xh, *xl, *Gh, *Gl, *Bph, *Bpl, *UWoh, *UWol;
    __nv_bfloat16 *WqTh, *WqTl, *WkTh, *WkTl, *VcTh, *VcTl, *WcTh, *WcTl, *UcTh, *UcTl, *Woh, *Wol;
    cudaGetSymbolAddress((void**)&H,    g_H);
    cudaGetSymbolAddress((void**)&xh,   g_xh);
    cudaGetSymbolAddress((void**)&xl,   g_xl);
    cudaGetSymbolAddress((void**)&Gh,   g_Gh);
    cudaGetSymbolAddress((void**)&Gl,   g_Gl);
    cudaGetSymbolAddress((void**)&Bph,  g_Bph);
    cudaGetSymbolAddress((void**)&Bpl,  g_Bpl);
    cudaGetSymbolAddress((void**)&UWoh, g_UWoh);
    cudaGetSymbolAddress((void**)&UWol, g_UWol);
    cudaGetSymbolAddress((void**)&WqTh, g_WqTh);
    cudaGetSymbolAddress((void**)&WqTl, g_WqTl);
    cudaGetSymbolAddress((void**)&WkTh, g_WkTh);
    cudaGetSymbolAddress((void**)&WkTl, g_WkTl);
    cudaGetSymbolAddress((void**)&VcTh, g_VcTh);
    cudaGetSymbolAddress((void**)&VcTl, g_VcTl);
    cudaGetSymbolAddress((void**)&WcTh, g_WcTh);
    cudaGetSymbolAddress((void**)&WcTl, g_WcTl);
    cudaGetSymbolAddress((void**)&UcTh, g_UcTh);
    cudaGetSymbolAddress((void**)&UcTl, g_UcTl);
    cudaGetSymbolAddress((void**)&Woh,  g_Woh);
    cudaGetSymbolAddress((void**)&Wol,  g_Wol);
    cudaGetSymbolAddress((void**)&bo,   g_bo);
    cudaGetSymbolAddress((void**)&cs,   g_cs);

    cudaFuncSetAttribute(gemm_prep, cudaFuncAttributeMaxDynamicSharedMemorySize, PRE_SMEM);
    cudaFuncSetAttribute(gemm_main<false, true>,  cudaFuncAttributeMaxDynamicSharedMemorySize, PRE_SMEM);
    cudaFuncSetAttribute(gemm_main<true,  false>, cudaFuncAttributeMaxDynamicSharedMemorySize, PRE_SMEM);

    // ---- prep: transposes/concats + bias fold + x split ----
    dim3 tgrid(32, 32, 10), tblk(32, 8);
    trans_batched<<<tgrid, tblk>>>(Wq, Wk, V_b, V_t, W_b, W_t, U_b, U_t, X_t, Wo,
                                   WqTh, WqTl, WkTh, WkTl, VcTh, VcTl, WcTh, WcTl,
                                   UcTh, UcTl, Bph, Bpl, Woh, Wol);
    bo_kernel<<<128, 256>>>(Wo, bias_b, bias_t, alpha, bo);
    split_x<<<4096, 256>>>(x, xh, xl);

    // ---- prep GEMMs: 96 tiles x 3 k-slices = 288 CTAs (one dual-CTA wave) ----
    dim3 gprep(96, 3);
    gemm_prep<<<gprep, 128, PRE_SMEM>>>(VcTh, VcTl, WqTh, WqTl, WcTh, WcTl, WkTh, WkTl,
                                        Woh, Wol, UcTh, UcTl, H);
    combine_prep<<<1024, 256>>>(H, Bph, Bpl, UWoh, UWol);

    // ---- main: H = x @ Bp^T  [8192, 1280], fused chunk-prefix epilogue ----
    dim3 gH(NPROJ / 128, MTOT / 128);
    gemm_main<false, true><<<gH, 128, PRE_SMEM>>>(xh, xl, Bph, Bpl, H, NPROJ, D_MODEL,
                                                  nullptr, cs);

    // ---- chunk offsets over cs ----
    scan_offsets<<<(BATCH * SCANC + 255) / 256, 256>>>(cs);

    // ---- fused apply + build G (bf16 split, 2 r per thread) ----
    apply_build<<<(MTOT * (RANK / 2) + 255) / 256, 256>>>(H, cs, alpha, Gh, Gl);

    // ---- out = G @ UWo^T + bo  [8192, 1024] ----
    dim3 gO(D_MODEL / 128, MTOT / 128);
    gemm_main<true, false><<<gO, 128, PRE_SMEM>>>(Gh, Gl, UWoh, UWol, out, D_MODEL, R2,
                                                  bo, nullptr);
}